// round 1
// baseline (speedup 1.0000x reference)
#include <cuda_runtime.h>
#include <cuda_bf16.h>
#include <cstdint>

// Problem constants (fixed by the dataset).
#define TREES 64
#define DNODES 255      // internal nodes per tree (2^8 - 1)
#define KLEAF 256       // leaves per tree
#define MFEAT 512       // features
#define CCLS 8          // classes
#define BATCH 4096

// Blocking
#define TT 16           // trees per block (gridDim.y = TREES/TT = 4)
#define BB 32           // batch rows per block
#define WB 8            // batch rows per warp (4 warps/block)

// Scratch (no cudaMalloc allowed): preprocessed one-hot feature index and 10*b1.
__device__ int   g_feat[TREES * DNODES];
__device__ float g_tb[TREES * DNODES];

// ---------------------------------------------------------------------------
// Preprocess: extract one-hot feature index from W1 rows, and tb = 10*b1.
// One warp per (t,d) row of 512 floats.
// ---------------------------------------------------------------------------
__global__ void prep_kernel(const float* __restrict__ W1,
                            const float* __restrict__ b1)
{
    int row = blockIdx.x * (blockDim.x >> 5) + (threadIdx.x >> 5);
    if (row >= TREES * DNODES) return;
    int lane = threadIdx.x & 31;

    const float4* w4 = reinterpret_cast<const float4*>(W1 + (size_t)row * MFEAT);
    int idx = 0;
#pragma unroll
    for (int i = 0; i < 4; i++) {
        float4 v = w4[i * 32 + lane];
        int base = (i * 32 + lane) * 4;
        if (v.x != 0.0f) idx = base + 0;
        if (v.y != 0.0f) idx = base + 1;
        if (v.z != 0.0f) idx = base + 2;
        if (v.w != 0.0f) idx = base + 3;
    }
#pragma unroll
    for (int off = 16; off; off >>= 1)
        idx = max(idx, __shfl_xor_sync(0xffffffffu, idx, off));
    if (lane == 0) {
        g_feat[row] = idx;
        g_tb[row]   = 10.0f * b1[row];
    }
}

// sigmoid(10*x + tb) via MUFU ex2 + rcp (rel err ~1e-7, safe for 1e-3 tol).
__device__ __forceinline__ float sigf(float xv, float tb)
{
    float z = fmaf(10.0f, xv, tb);
    float u = z * -1.44269504088896f;   // -z * log2(e)
    float e;
    asm("ex2.approx.f32 %0, %1;" : "=f"(e) : "f"(u));
    float r;
    asm("rcp.approx.f32 %0, %1;" : "=f"(r) : "f"(1.0f + e));
    return r;                            // 1 / (1 + exp(-z))
}

// ---------------------------------------------------------------------------
// Main kernel. Block: 128 threads = 4 warps; covers BB=32 batch rows x TT=16
// trees. Warp w owns batch rows [8w, 8w+8). Lane owns the leaf subtree
// k in [8*lane, 8*lane+8) -> Cw[t] lives in 64 registers per lane, reused
// across 8 batch rows. Leaf probs via hierarchical sigmoid products along
// hardcoded heap paths (identical to reference _build_path_masks).
// ---------------------------------------------------------------------------
__global__ __launch_bounds__(128, 2)
void forest_kernel(const float* __restrict__ x,
                   const float* __restrict__ Cw,
                   float* __restrict__ out)
{
    extern __shared__ float smem[];
    float*  xs    = smem;                               // BB*512 floats (64 KB)
    float4* cwsh4 = reinterpret_cast<float4*>(smem + BB * 512);   // 512 float4 (8 KB)
    float*  sarr  = smem + BB * 512 + 2048;             // 4 warps * 32 (512 B)
    int*    ftsh  = reinterpret_cast<int*>(sarr + 4 * 32);        // 256 ints
    float*  tbsh  = reinterpret_cast<float*>(ftsh + 256);         // 256 floats

    const int tid   = threadIdx.x;
    const int lane  = tid & 31;
    const int warp  = tid >> 5;
    const int bbase = blockIdx.x * BB;
    const int tbase = blockIdx.y * TT;

    // Stage 32 x-rows (64 KB) cooperatively, coalesced float4.
    {
        const float4* x4  = reinterpret_cast<const float4*>(x + (size_t)bbase * MFEAT);
        float4*       xs4 = reinterpret_cast<float4*>(xs);
#pragma unroll
        for (int i = 0; i < 32; i++)
            xs4[i * 128 + tid] = x4[i * 128 + tid];
    }

    float acc[WB][CCLS];
#pragma unroll
    for (int b = 0; b < WB; b++)
#pragma unroll
        for (int c = 0; c < CCLS; c++) acc[b][c] = 0.0f;

    float* swp = sarr + warp * 32;

    for (int tt = 0; tt < TT; tt++) {
        const int t = tbase + tt;
        __syncthreads();   // protect shared from previous iteration / xs ready

        // Stage per-tree tables.
        for (int i = tid; i < DNODES; i += 128) {
            ftsh[i] = g_feat[t * DNODES + i];
            tbsh[i] = g_tb[t * DNODES + i];
        }
        // Stage Cw[t] (2048 floats) XOR-swizzled so per-lane LDS.128 is
        // bank-conflict-free (lane stride is 256 B otherwise -> same bank quad).
        {
            const float4* cw4 = reinterpret_cast<const float4*>(Cw + (size_t)t * KLEAF * CCLS);
            for (int q = tid; q < 512; q += 128)
                cwsh4[q ^ ((q >> 4) & 7)] = cw4[q];
        }
        __syncthreads();

        // Per-lane register copy of Cw for its 8 leaves (64 regs).
        float cwr[8][8];
#pragma unroll
        for (int j = 0; j < 8; j++) {
            int k = lane * 8 + j;
#pragma unroll
            for (int h = 0; h < 2; h++) {
                int p4 = (k * 2 + h) ^ (lane & 7);
                float4 v = cwsh4[p4];
                cwr[j][4 * h + 0] = v.x;
                cwr[j][4 * h + 1] = v.y;
                cwr[j][4 * h + 2] = v.z;
                cwr[j][4 * h + 3] = v.w;
            }
        }

        // Per-lane node tables (reused across 8 batch rows):
        // shared prefix node (levels 0..4, nodes 0..30) handled by lanes 0..30;
        // lane-private subtree nodes: level5: 31+lane, level6: 63+2lane{,+1},
        // level7: 127+4lane+{0..3}.
        int   fpre = 0;  float tpre = 0.0f;
        if (lane < 31) { fpre = ftsh[lane]; tpre = tbsh[lane]; }
        const int   f5  = ftsh[31 + lane];       const float t5  = tbsh[31 + lane];
        const int   f6a = ftsh[63 + 2 * lane];   const float t6a = tbsh[63 + 2 * lane];
        const int   f6b = ftsh[64 + 2 * lane];   const float t6b = tbsh[64 + 2 * lane];
        int f7[4]; float t7[4];
#pragma unroll
        for (int i = 0; i < 4; i++) {
            f7[i] = ftsh[127 + 4 * lane + i];
            t7[i] = tbsh[127 + 4 * lane + i];
        }

#pragma unroll 1
        for (int b = 0; b < WB; b++) {
            const float* xr = xs + (warp * WB + b) * MFEAT;
            __syncwarp();                      // prior iteration's sarr reads done
            if (lane < 31) swp[lane] = sigf(xr[fpre], tpre);
            float s5  = sigf(xr[f5],  t5);
            float s6a = sigf(xr[f6a], t6a);
            float s6b = sigf(xr[f6b], t6b);
            float s70 = sigf(xr[f7[0]], t7[0]);
            float s71 = sigf(xr[f7[1]], t7[1]);
            float s72 = sigf(xr[f7[2]], t7[2]);
            float s73 = sigf(xr[f7[3]], t7[3]);
            __syncwarp();

            // Prefix product over levels 0..4 (heap walk; bit=1 -> right -> s).
            float p = 1.0f;
            int node = 0;
#pragma unroll
            for (int l = 0; l < 5; l++) {
                int bit = (lane >> (4 - l)) & 1;
                float s = swp[node];
                p *= bit ? s : (1.0f - s);
                node = 2 * node + 1 + bit;
            }
            // Subtree expansion (levels 5..7) -> 8 leaf probabilities.
            float pA  = p  * (1.0f - s5),  pB  = p  * s5;
            float p00 = pA * (1.0f - s6a), p01 = pA * s6a;
            float p10 = pB * (1.0f - s6b), p11 = pB * s6b;
            float P[8];
            P[0] = p00 * (1.0f - s70);  P[1] = p00 * s70;
            P[2] = p01 * (1.0f - s71);  P[3] = p01 * s71;
            P[4] = p10 * (1.0f - s72);  P[5] = p10 * s72;
            P[6] = p11 * (1.0f - s73);  P[7] = p11 * s73;

            // Contraction with register-resident Cw (64 FFMA).
#pragma unroll
            for (int j = 0; j < 8; j++)
#pragma unroll
                for (int c = 0; c < CCLS; c++)
                    acc[b][c] = fmaf(P[j], cwr[j][c], acc[b][c]);
        }
    }

    // Cross-lane reduction (leaves were split over lanes), once per block.
#pragma unroll
    for (int b = 0; b < WB; b++)
#pragma unroll
        for (int c = 0; c < CCLS; c++) {
            float v = acc[b][c];
#pragma unroll
            for (int off = 16; off; off >>= 1)
                v += __shfl_xor_sync(0xffffffffu, v, off);
            acc[b][c] = v;
        }

    if (lane < CCLS) {
        const float inv_t = 1.0f / (float)TREES;
#pragma unroll
        for (int b = 0; b < WB; b++) {
            int brow = bbase + warp * WB + b;
            atomicAdd(&out[brow * CCLS + lane], acc[b][lane] * inv_t);
        }
    }
}

// ---------------------------------------------------------------------------
extern "C" void kernel_launch(void* const* d_in, const int* in_sizes, int n_in,
                              void* d_out, int out_size)
{
    // Identify inputs by element count (order per metadata: input, W1, b1,
    // Bpos, Bneg, Cw — Bpos/Bneg are structurally fixed and unused).
    const float* x  = nullptr;
    const float* W1 = nullptr;
    const float* b1 = nullptr;
    const float* Cw = nullptr;
    for (int i = 0; i < n_in; i++) {
        switch (in_sizes[i]) {
            case BATCH * MFEAT:          x  = (const float*)d_in[i]; break; // 2097152
            case TREES * DNODES * MFEAT: W1 = (const float*)d_in[i]; break; // 8355840
            case TREES * DNODES:         b1 = (const float*)d_in[i]; break; // 16320
            case TREES * KLEAF * CCLS:   Cw = (const float*)d_in[i]; break; // 131072
            default: break;                                                 // Bpos/Bneg
        }
    }
    float* out = (float*)d_out;

    // Opt-in to >48KB dynamic shared memory (idempotent, host-side, capture-safe).
    static const size_t smem_bytes =
        (size_t)(BB * 512 + 2048 + 4 * 32 + 256 + 256) * 4;
    cudaFuncSetAttribute(forest_kernel,
                         cudaFuncAttributeMaxDynamicSharedMemorySize,
                         (int)smem_bytes);

    cudaMemsetAsync(d_out, 0, (size_t)out_size * sizeof(float), 0);

    {
        int rows = TREES * DNODES;
        int warps_per_block = 8;
        int blocks = (rows + warps_per_block - 1) / warps_per_block;
        prep_kernel<<<blocks, warps_per_block * 32>>>(W1, b1);
    }

    dim3 grid(BATCH / BB, TREES / TT);
    forest_kernel<<<grid, 128, smem_bytes>>>(x, Cw, out);
}

// round 3
// speedup vs baseline: 1.3496x; 1.3496x over previous
#include <cuda_runtime.h>
#include <cuda_bf16.h>
#include <cstdint>

// Problem constants (fixed by the dataset).
#define TREES 64
#define DNODES 255      // internal nodes per tree (2^8 - 1)
#define KLEAF 256       // leaves per tree
#define MFEAT 512       // features
#define CCLS 8          // classes
#define BATCH 4096

// Blocking
#define TT 16           // trees per block (gridDim.y = TREES/TT = 4)
#define BB 32           // batch rows per block
#define WB 8            // batch rows per warp (4 warps/block)

// Scratch (no cudaMalloc allowed): preprocessed one-hot feature index and 5*b1
// (half-logit bias for the tanh form of the sigmoid).
__device__ int   g_feat[TREES * DNODES];
__device__ float g_tb[TREES * DNODES];

// ---------------------------------------------------------------------------
// Preprocess: extract one-hot feature index from W1 rows, and tbh = 5*b1.
// One warp per (t,d) row of 512 floats.
// ---------------------------------------------------------------------------
__global__ void prep_kernel(const float* __restrict__ W1,
                            const float* __restrict__ b1)
{
    int row = blockIdx.x * (blockDim.x >> 5) + (threadIdx.x >> 5);
    if (row >= TREES * DNODES) return;
    int lane = threadIdx.x & 31;

    const float4* w4 = reinterpret_cast<const float4*>(W1 + (size_t)row * MFEAT);
    int idx = 0;
#pragma unroll
    for (int i = 0; i < 4; i++) {
        float4 v = w4[i * 32 + lane];
        int base = (i * 32 + lane) * 4;
        if (v.x != 0.0f) idx = base + 0;
        if (v.y != 0.0f) idx = base + 1;
        if (v.z != 0.0f) idx = base + 2;
        if (v.w != 0.0f) idx = base + 3;
    }
#pragma unroll
    for (int off = 16; off; off >>= 1)
        idx = max(idx, __shfl_xor_sync(0xffffffffu, idx, off));
    if (lane == 0) {
        g_feat[row] = idx;
        g_tb[row]   = 5.0f * b1[row];   // sigmoid(10x+10b) = 0.5 + 0.5*tanh(5x+5b)
    }
}

// th = tanh(5*x + tbh) via single MUFU.TANH.
__device__ __forceinline__ float tanh5(float xv, float tbh)
{
    float z = fmaf(5.0f, xv, tbh);
    float r;
    asm("tanh.approx.f32 %0, %1;" : "=f"(r) : "f"(z));
    return r;
}

// Pack two floats into a 64-bit register pair.
__device__ __forceinline__ unsigned long long pk2(float lo, float hi)
{
    unsigned long long r;
    asm("mov.b64 %0, {%1, %2};" : "=l"(r) : "f"(lo), "f"(hi));
    return r;
}
// Packed dual FFMA (Blackwell FFMA2, PTX-only).
__device__ __forceinline__ unsigned long long ffma2(unsigned long long a,
                                                    unsigned long long b,
                                                    unsigned long long c)
{
    unsigned long long d;
    asm("fma.rn.f32x2 %0, %1, %2, %3;" : "=l"(d) : "l"(a), "l"(b), "l"(c));
    return d;
}
__device__ __forceinline__ void upk2(unsigned long long v, float& lo, float& hi)
{
    asm("mov.b64 {%0, %1}, %2;" : "=f"(lo), "=f"(hi) : "l"(v));
}

// ---------------------------------------------------------------------------
// Main kernel. Block: 128 threads = 4 warps; covers BB=32 batch rows x TT=16
// trees. Warp w owns batch rows [8w, 8w+8). Lane owns the leaf subtree
// k in [8*lane, 8*lane+8) -> Cw[t] lives in 32 x f32x2 registers per lane.
// Prefix levels 0..4 (nodes 0..30) are computed by lanes 0..30 and exchanged
// with 5 INDEPENDENT shfls (node index is a closed form of the lane id):
//   n_l = 2^l - 1 + (lane >> (5-l)).
// ---------------------------------------------------------------------------
__global__ __launch_bounds__(128, 3)
void forest_kernel(const float* __restrict__ x,
                   const float* __restrict__ Cw,
                   float* __restrict__ out)
{
    extern __shared__ float smem[];
    float*  xs    = smem;                                       // 32*512 floats (64 KB)
    float4* cwsh4 = reinterpret_cast<float4*>(smem + BB * 512); // 512 float4 (8 KB)
    int*    ftsh  = reinterpret_cast<int*>(smem + BB * 512 + 2048);   // 256 ints
    float*  tbsh  = reinterpret_cast<float*>(ftsh + 256);             // 256 floats

    const int tid   = threadIdx.x;
    const int lane  = tid & 31;
    const int warp  = tid >> 5;
    const int bbase = blockIdx.x * BB;
    const int tbase = blockIdx.y * TT;

    // Stage 32 x-rows (64 KB) cooperatively, coalesced float4.
    {
        const float4* x4  = reinterpret_cast<const float4*>(x + (size_t)bbase * MFEAT);
        float4*       xs4 = reinterpret_cast<float4*>(xs);
#pragma unroll
        for (int i = 0; i < 32; i++)
            xs4[i * 128 + tid] = x4[i * 128 + tid];
    }

    // Tree-independent per-lane prefix constants.
    const int pn = (lane < 31) ? lane : 0;        // node this lane evaluates
    const int n1 = 1  + (lane >> 4);
    const int n2 = 3  + (lane >> 3);
    const int n3 = 7  + (lane >> 2);
    const int n4 = 15 + (lane >> 1);
    const float sg0 = (lane & 16) ? 0.5f : -0.5f; // level-l factor = 0.5 + sg*th
    const float sg1 = (lane & 8)  ? 0.5f : -0.5f;
    const float sg2 = (lane & 4)  ? 0.5f : -0.5f;
    const float sg3 = (lane & 2)  ? 0.5f : -0.5f;
    const float sg4 = (lane & 1)  ? 0.5f : -0.5f;

    unsigned long long acc2[WB][4];
#pragma unroll
    for (int b = 0; b < WB; b++)
#pragma unroll
        for (int q = 0; q < 4; q++) acc2[b][q] = 0ull;

    for (int tt = 0; tt < TT; tt++) {
        const int t = tbase + tt;
        __syncthreads();   // xs ready / previous iteration's shared reads done

        // Stage per-tree node tables.
        for (int i = tid; i < DNODES; i += 128) {
            ftsh[i] = g_feat[t * DNODES + i];
            tbsh[i] = g_tb[t * DNODES + i];
        }
        // Stage Cw[t] (2048 floats) XOR-swizzled so per-lane LDS.128 is
        // bank-conflict-free.
        {
            const float4* cw4 = reinterpret_cast<const float4*>(Cw + (size_t)t * KLEAF * CCLS);
            for (int q = tid; q < 512; q += 128)
                cwsh4[q ^ ((q >> 4) & 7)] = cw4[q];
        }
        __syncthreads();

        // Per-lane packed Cw copy for its 8 leaves (32 x f32x2 = 64 regs).
        unsigned long long cwr2[8][4];
#pragma unroll
        for (int j = 0; j < 8; j++) {
            int k = lane * 8 + j;
#pragma unroll
            for (int h = 0; h < 2; h++) {
                int p4 = (k * 2 + h) ^ (lane & 7);
                float4 v = cwsh4[p4];
                cwr2[j][2 * h + 0] = pk2(v.x, v.y);
                cwr2[j][2 * h + 1] = pk2(v.z, v.w);
            }
        }

        // Per-lane node parameters.
        const int   fpre = ftsh[pn];             const float tpre = tbsh[pn];
        const int   f5   = ftsh[31 + lane];      const float t5   = tbsh[31 + lane];
        const int   f6a  = ftsh[63 + 2 * lane];  const float t6a  = tbsh[63 + 2 * lane];
        const int   f6b  = ftsh[64 + 2 * lane];  const float t6b  = tbsh[64 + 2 * lane];
        int f7[4]; float t7[4];
#pragma unroll
        for (int i = 0; i < 4; i++) {
            f7[i] = ftsh[127 + 4 * lane + i];
            t7[i] = tbsh[127 + 4 * lane + i];
        }

#pragma unroll 1
        for (int b = 0; b < WB; b++) {
            const float* xr = xs + (warp * WB + b) * MFEAT;

            // 8 independent gather+tanh chains.
            float thp = tanh5(xr[fpre],  tpre);
            float th5 = tanh5(xr[f5],    t5);
            float th6a = tanh5(xr[f6a],  t6a);
            float th6b = tanh5(xr[f6b],  t6b);
            float th70 = tanh5(xr[f7[0]], t7[0]);
            float th71 = tanh5(xr[f7[1]], t7[1]);
            float th72 = tanh5(xr[f7[2]], t7[2]);
            float th73 = tanh5(xr[f7[3]], t7[3]);

            // Prefix product over levels 0..4 — 5 independent shfls.
            float u0 = __shfl_sync(0xffffffffu, thp, 0);
            float u1 = __shfl_sync(0xffffffffu, thp, n1);
            float u2 = __shfl_sync(0xffffffffu, thp, n2);
            float u3 = __shfl_sync(0xffffffffu, thp, n3);
            float u4 = __shfl_sync(0xffffffffu, thp, n4);
            float g0 = fmaf(sg0, u0, 0.5f);
            float g1 = fmaf(sg1, u1, 0.5f);
            float g2 = fmaf(sg2, u2, 0.5f);
            float g3 = fmaf(sg3, u3, 0.5f);
            float g4 = fmaf(sg4, u4, 0.5f);
            float p = (g0 * g1) * (g2 * g3) * g4;

            // Subtree expansion (levels 5..7) -> 8 leaf probabilities.
            float f5n = fmaf(-0.5f, th5, 0.5f),  f5p = fmaf(0.5f, th5, 0.5f);
            float pA = p * f5n, pB = p * f5p;
            float a6n = fmaf(-0.5f, th6a, 0.5f), a6p = fmaf(0.5f, th6a, 0.5f);
            float b6n = fmaf(-0.5f, th6b, 0.5f), b6p = fmaf(0.5f, th6b, 0.5f);
            float p00 = pA * a6n, p01 = pA * a6p;
            float p10 = pB * b6n, p11 = pB * b6p;
            float c0n = fmaf(-0.5f, th70, 0.5f), c0p = fmaf(0.5f, th70, 0.5f);
            float c1n = fmaf(-0.5f, th71, 0.5f), c1p = fmaf(0.5f, th71, 0.5f);
            float c2n = fmaf(-0.5f, th72, 0.5f), c2p = fmaf(0.5f, th72, 0.5f);
            float c3n = fmaf(-0.5f, th73, 0.5f), c3p = fmaf(0.5f, th73, 0.5f);
            float P[8];
            P[0] = p00 * c0n;  P[1] = p00 * c0p;
            P[2] = p01 * c1n;  P[3] = p01 * c1p;
            P[4] = p10 * c2n;  P[5] = p10 * c2p;
            P[6] = p11 * c3n;  P[7] = p11 * c3p;

            // Contraction with register-resident Cw: 32 FFMA2.
#pragma unroll
            for (int j = 0; j < 8; j++) {
                unsigned long long pp = pk2(P[j], P[j]);
#pragma unroll
                for (int q = 0; q < 4; q++)
                    acc2[b][q] = ffma2(pp, cwr2[j][q], acc2[b][q]);
            }
        }
    }

    // Unpack, cross-lane reduce (leaves were split over lanes), write out.
    const float inv_t = 1.0f / (float)TREES;
#pragma unroll
    for (int b = 0; b < WB; b++) {
        float acc[CCLS];
#pragma unroll
        for (int q = 0; q < 4; q++)
            upk2(acc2[b][q], acc[2 * q], acc[2 * q + 1]);
#pragma unroll
        for (int c = 0; c < CCLS; c++) {
            float v = acc[c];
#pragma unroll
            for (int off = 16; off; off >>= 1)
                v += __shfl_xor_sync(0xffffffffu, v, off);
            acc[c] = v;
        }
        if (lane < CCLS) {
            int brow = bbase + warp * WB + b;
            atomicAdd(&out[brow * CCLS + lane], acc[lane] * inv_t);
        }
    }
}

// ---------------------------------------------------------------------------
extern "C" void kernel_launch(void* const* d_in, const int* in_sizes, int n_in,
                              void* d_out, int out_size)
{
    // Identify inputs by element count (order per metadata: input, W1, b1,
    // Bpos, Bneg, Cw — Bpos/Bneg are structurally fixed and unused).
    const float* x  = nullptr;
    const float* W1 = nullptr;
    const float* b1 = nullptr;
    const float* Cw = nullptr;
    for (int i = 0; i < n_in; i++) {
        switch (in_sizes[i]) {
            case BATCH * MFEAT:          x  = (const float*)d_in[i]; break; // 2097152
            case TREES * DNODES * MFEAT: W1 = (const float*)d_in[i]; break; // 8355840
            case TREES * DNODES:         b1 = (const float*)d_in[i]; break; // 16320
            case TREES * KLEAF * CCLS:   Cw = (const float*)d_in[i]; break; // 131072
            default: break;                                                 // Bpos/Bneg
        }
    }
    float* out = (float*)d_out;

    static const size_t smem_bytes =
        (size_t)(BB * 512 + 2048 + 256 + 256) * 4;
    cudaFuncSetAttribute(forest_kernel,
                         cudaFuncAttributeMaxDynamicSharedMemorySize,
                         (int)smem_bytes);

    cudaMemsetAsync(d_out, 0, (size_t)out_size * sizeof(float), 0);

    {
        int rows = TREES * DNODES;
        int warps_per_block = 8;
        int blocks = (rows + warps_per_block - 1) / warps_per_block;
        prep_kernel<<<blocks, warps_per_block * 32>>>(W1, b1);
    }

    dim3 grid(BATCH / BB, TREES / TT);
    forest_kernel<<<grid, 128, smem_bytes>>>(x, Cw, out);
}